// round 2
// baseline (speedup 1.0000x reference)
#include <cuda_runtime.h>
#include <cuda_bf16.h>

// Problem constants
constexpr int B_SZ    = 2;
constexpr int S_LEN   = 2048;
constexpr int D_MODEL = 1024;
constexpr int NHEAD   = 16;
constexpr int DKH     = 64;              // d_k per head
constexpr int NTOK    = B_SZ * S_LEN;    // 4096 rows for projection GEMMs

// Scratch (device globals: allocation-free per harness rules)
__device__ float g_q[NTOK * D_MODEL];
__device__ float g_k[NTOK * D_MODEL];
__device__ float g_v[NTOK * D_MODEL];
__device__ float g_attn[NTOK * D_MODEL];

// ---------------------------------------------------------------------------
// GEMM: Y[M,N] = X[M,K] @ W[N,K]^T + bias[N]   (nn.Linear semantics)
// 128x128 block tile, BK=8, 256 threads, 8x8 microtile (split 4+4).
// ---------------------------------------------------------------------------
__global__ __launch_bounds__(256) void gemm_bias_kernel(
    const float* __restrict__ X, const float* __restrict__ W,
    const float* __restrict__ bias, float* __restrict__ Y,
    int M, int N, int K)
{
    __shared__ float Xs[8][128];
    __shared__ float Ws[8][128];

    const int tid = threadIdx.x;
    const int tx  = tid & 15;        // 0..15 -> N microtile
    const int ty  = tid >> 4;        // 0..15 -> M microtile
    const int m0  = blockIdx.y * 128;
    const int n0  = blockIdx.x * 128;

    const int lrow = tid >> 1;           // 0..127
    const int lc4  = (tid & 1) * 4;      // 0 or 4

    const float* xp = X + (size_t)(m0 + lrow) * K + lc4;
    const float* wp = W + (size_t)(n0 + lrow) * K + lc4;

    float acc[8][8];
#pragma unroll
    for (int i = 0; i < 8; ++i)
#pragma unroll
        for (int j = 0; j < 8; ++j) acc[i][j] = 0.0f;

    const int nk = K >> 3;
    float4 xf = *(const float4*)xp;
    float4 wf = *(const float4*)wp;

    for (int kt = 0; kt < nk; ++kt) {
        Xs[lc4 + 0][lrow] = xf.x; Xs[lc4 + 1][lrow] = xf.y;
        Xs[lc4 + 2][lrow] = xf.z; Xs[lc4 + 3][lrow] = xf.w;
        Ws[lc4 + 0][lrow] = wf.x; Ws[lc4 + 1][lrow] = wf.y;
        Ws[lc4 + 2][lrow] = wf.z; Ws[lc4 + 3][lrow] = wf.w;
        __syncthreads();

        if (kt + 1 < nk) {
            xf = *(const float4*)(xp + (size_t)(kt + 1) * 8);
            wf = *(const float4*)(wp + (size_t)(kt + 1) * 8);
        }

#pragma unroll
        for (int kk = 0; kk < 8; ++kk) {
            float4 a0 = *(const float4*)&Xs[kk][ty * 4];
            float4 a1 = *(const float4*)&Xs[kk][64 + ty * 4];
            float4 b0 = *(const float4*)&Ws[kk][tx * 4];
            float4 b1 = *(const float4*)&Ws[kk][64 + tx * 4];
            float av[8] = {a0.x, a0.y, a0.z, a0.w, a1.x, a1.y, a1.z, a1.w};
            float bv[8] = {b0.x, b0.y, b0.z, b0.w, b1.x, b1.y, b1.z, b1.w};
#pragma unroll
            for (int i = 0; i < 8; ++i)
#pragma unroll
                for (int j = 0; j < 8; ++j)
                    acc[i][j] += av[i] * bv[j];
        }
        __syncthreads();
    }

    // Epilogue: add bias, vectorized stores
    float4 bi0 = *(const float4*)(bias + n0 + tx * 4);
    float4 bi1 = *(const float4*)(bias + n0 + 64 + tx * 4);
    float bb[8] = {bi0.x, bi0.y, bi0.z, bi0.w, bi1.x, bi1.y, bi1.z, bi1.w};

#pragma unroll
    for (int half = 0; half < 2; ++half) {
#pragma unroll
        for (int i = 0; i < 4; ++i) {
            int ai = half * 4 + i;
            int r  = m0 + half * 64 + ty * 4 + i;
            float* yp = Y + (size_t)r * N + n0;
            float4 o0 = make_float4(acc[ai][0] + bb[0], acc[ai][1] + bb[1],
                                    acc[ai][2] + bb[2], acc[ai][3] + bb[3]);
            float4 o1 = make_float4(acc[ai][4] + bb[4], acc[ai][5] + bb[5],
                                    acc[ai][6] + bb[6], acc[ai][7] + bb[7]);
            *(float4*)(yp + tx * 4)      = o0;
            *(float4*)(yp + 64 + tx * 4) = o1;
        }
    }
}

// ---------------------------------------------------------------------------
// Flash attention: one block per (q_tile=64, head, batch).
// Online softmax; 4x4 microtiles; row-mates form one half-warp -> width-16
// shuffle reductions for row max/sum.
// ---------------------------------------------------------------------------
constexpr int TQ = 64;
constexpr int TK = 64;
constexpr int QPAD = DKH + 4;   // 68: float4-aligned, reduces conflicts
constexpr int PPAD = TK + 1;    // 65

// dynamic smem layout (floats): q[64*68] k[64*68] v[64*68] p[64*65]
constexpr int SM_Q = 0;
constexpr int SM_K = SM_Q + TQ * QPAD;
constexpr int SM_V = SM_K + TK * QPAD;
constexpr int SM_P = SM_V + TK * QPAD;
constexpr int SM_TOTAL_FLOATS = SM_P + TQ * PPAD;
constexpr int SM_BYTES = SM_TOTAL_FLOATS * 4;   // 68864 bytes

__global__ __launch_bounds__(256) void attn_kernel(
    const float* __restrict__ q, const float* __restrict__ k,
    const float* __restrict__ v, float* __restrict__ o)
{
    extern __shared__ float sm[];
    float (*q_s)[QPAD] = (float(*)[QPAD])(sm + SM_Q);
    float (*k_s)[QPAD] = (float(*)[QPAD])(sm + SM_K);
    float (*v_s)[QPAD] = (float(*)[QPAD])(sm + SM_V);
    float (*p_s)[PPAD] = (float(*)[PPAD])(sm + SM_P);

    const int tid = threadIdx.x;
    const int tx  = tid & 15;
    const int ty  = tid >> 4;
    const int qt  = blockIdx.x;
    const int h   = blockIdx.y;
    const int b   = blockIdx.z;

    const size_t base = ((size_t)b * S_LEN) * D_MODEL + (size_t)h * DKH;
    const float* qb = q + base + (size_t)(qt * TQ) * D_MODEL;
    const float* kb = k + base;
    const float* vb = v + base;

    // Load Q tile (persistent for whole block)
#pragma unroll
    for (int f = tid; f < TQ * DKH / 4; f += 256) {
        int r = f >> 4;
        int c = (f & 15) << 2;
        *(float4*)&q_s[r][c] = *(const float4*)(qb + (size_t)r * D_MODEL + c);
    }

    float acc[4][4];
    float m_i[4], l_i[4];
#pragma unroll
    for (int i = 0; i < 4; ++i) {
        m_i[i] = -1e30f;
        l_i[i] = 0.0f;
#pragma unroll
        for (int j = 0; j < 4; ++j) acc[i][j] = 0.0f;
    }

    const float scale = 0.125f;  // 1/sqrt(64)

    for (int kt = 0; kt < S_LEN / TK; ++kt) {
        const float* kp = kb + (size_t)(kt * TK) * D_MODEL;
        const float* vp = vb + (size_t)(kt * TK) * D_MODEL;
#pragma unroll
        for (int f = tid; f < TK * DKH / 4; f += 256) {
            int r = f >> 4;
            int c = (f & 15) << 2;
            *(float4*)&k_s[r][c] = *(const float4*)(kp + (size_t)r * D_MODEL + c);
            *(float4*)&v_s[r][c] = *(const float4*)(vp + (size_t)r * D_MODEL + c);
        }
        __syncthreads();

        // ---- scores: s[i][j] = q_row(ty*4+i) . k_row(tx*4+j) ----
        float s[4][4];
#pragma unroll
        for (int i = 0; i < 4; ++i)
#pragma unroll
            for (int j = 0; j < 4; ++j) s[i][j] = 0.0f;

#pragma unroll
        for (int d4 = 0; d4 < DKH; d4 += 4) {
            float4 a[4], bbk[4];
#pragma unroll
            for (int i = 0; i < 4; ++i) a[i]   = *(const float4*)&q_s[ty * 4 + i][d4];
#pragma unroll
            for (int j = 0; j < 4; ++j) bbk[j] = *(const float4*)&k_s[tx * 4 + j][d4];
#pragma unroll
            for (int i = 0; i < 4; ++i)
#pragma unroll
                for (int j = 0; j < 4; ++j) {
                    s[i][j] += a[i].x * bbk[j].x;
                    s[i][j] += a[i].y * bbk[j].y;
                    s[i][j] += a[i].z * bbk[j].z;
                    s[i][j] += a[i].w * bbk[j].w;
                }
        }

        // ---- online softmax per query row ----
#pragma unroll
        for (int i = 0; i < 4; ++i) {
            float s0 = s[i][0] * scale, s1 = s[i][1] * scale;
            float s2 = s[i][2] * scale, s3 = s[i][3] * scale;
            float tmax = fmaxf(fmaxf(s0, s1), fmaxf(s2, s3));
#pragma unroll
            for (int off = 8; off >= 1; off >>= 1)
                tmax = fmaxf(tmax, __shfl_xor_sync(0xffffffffu, tmax, off, 16));
            float newm = fmaxf(m_i[i], tmax);
            float p0 = __expf(s0 - newm), p1 = __expf(s1 - newm);
            float p2 = __expf(s2 - newm), p3 = __expf(s3 - newm);
            float psum = p0 + p1 + p2 + p3;
#pragma unroll
            for (int off = 8; off >= 1; off >>= 1)
                psum += __shfl_xor_sync(0xffffffffu, psum, off, 16);
            float alpha = __expf(m_i[i] - newm);
            l_i[i] = l_i[i] * alpha + psum;
            m_i[i] = newm;
#pragma unroll
            for (int j = 0; j < 4; ++j) acc[i][j] *= alpha;
            int r = ty * 4 + i;
            p_s[r][tx * 4 + 0] = p0;
            p_s[r][tx * 4 + 1] = p1;
            p_s[r][tx * 4 + 2] = p2;
            p_s[r][tx * 4 + 3] = p3;
        }
        __syncthreads();

        // ---- PV: acc[i][j] += sum_j' p[row][j'] * v[j'][dim] ----
#pragma unroll 8
        for (int jk = 0; jk < TK; ++jk) {
            float4 bv = *(const float4*)&v_s[jk][tx * 4];
#pragma unroll
            for (int i = 0; i < 4; ++i) {
                float a = p_s[ty * 4 + i][jk];
                acc[i][0] += a * bv.x;
                acc[i][1] += a * bv.y;
                acc[i][2] += a * bv.z;
                acc[i][3] += a * bv.w;
            }
        }
        __syncthreads();
    }

    // ---- epilogue: divide by l, write out (same [B,S,D] layout) ----
#pragma unroll
    for (int i = 0; i < 4; ++i) {
        float inv = 1.0f / l_i[i];
        float4 r4 = make_float4(acc[i][0] * inv, acc[i][1] * inv,
                                acc[i][2] * inv, acc[i][3] * inv);
        size_t row = (size_t)(qt * TQ + ty * 4 + i);
        *(float4*)(o + base + row * D_MODEL + tx * 4) = r4;
    }
}

// ---------------------------------------------------------------------------
// kernel_launch
// Inputs (metadata order): Q K V Wq bq Wk bk Wv bv Wo bo ; output float32
// ---------------------------------------------------------------------------
extern "C" void kernel_launch(void* const* d_in, const int* in_sizes, int n_in,
                              void* d_out, int out_size)
{
    const float* Q  = (const float*)d_in[0];
    const float* K  = (const float*)d_in[1];
    const float* V  = (const float*)d_in[2];
    const float* Wq = (const float*)d_in[3];
    const float* bq = (const float*)d_in[4];
    const float* Wk = (const float*)d_in[5];
    const float* bk = (const float*)d_in[6];
    const float* Wv = (const float*)d_in[7];
    const float* bv = (const float*)d_in[8];
    const float* Wo = (const float*)d_in[9];
    const float* bo = (const float*)d_in[10];
    float* out = (float*)d_out;

    float *gq, *gk, *gv, *ga;
    cudaGetSymbolAddress((void**)&gq, g_q);
    cudaGetSymbolAddress((void**)&gk, g_k);
    cudaGetSymbolAddress((void**)&gv, g_v);
    cudaGetSymbolAddress((void**)&ga, g_attn);

    cudaFuncSetAttribute(attn_kernel,
                         cudaFuncAttributeMaxDynamicSharedMemorySize, SM_BYTES);

    dim3 gblock(256);
    dim3 ggrid(D_MODEL / 128, NTOK / 128);  // (8, 32)

    gemm_bias_kernel<<<ggrid, gblock>>>(Q, Wq, bq, gq, NTOK, D_MODEL, D_MODEL);
    gemm_bias_kernel<<<ggrid, gblock>>>(K, Wk, bk, gk, NTOK, D_MODEL, D_MODEL);
    gemm_bias_kernel<<<ggrid, gblock>>>(V, Wv, bv, gv, NTOK, D_MODEL, D_MODEL);

    dim3 agrid(S_LEN / TQ, NHEAD, B_SZ);    // (32, 16, 2)
    attn_kernel<<<agrid, 256, SM_BYTES>>>(gq, gk, gv, ga);

    gemm_bias_kernel<<<ggrid, gblock>>>(ga, Wo, bo, out, NTOK, D_MODEL, D_MODEL);
}

// round 4
// speedup vs baseline: 1.2879x; 1.2879x over previous
#include <cuda_runtime.h>
#include <cuda_bf16.h>
#include <cstdint>

// Problem constants
constexpr int B_SZ    = 2;
constexpr int S_LEN   = 2048;
constexpr int D_MODEL = 1024;
constexpr int NHEAD   = 16;
constexpr int DKH     = 64;
constexpr int NTOK    = B_SZ * S_LEN;    // 4096

// Scratch (device globals: allocation-free per harness rules)
__device__ float g_q[NTOK * D_MODEL];
__device__ float g_k[NTOK * D_MODEL];
__device__ float g_v[NTOK * D_MODEL];
__device__ float g_attn[NTOK * D_MODEL];
__device__ __nv_bfloat16 g_xhi[NTOK * D_MODEL];
__device__ __nv_bfloat16 g_xlo[NTOK * D_MODEL];
__device__ __nv_bfloat16 g_whi[D_MODEL * D_MODEL];
__device__ __nv_bfloat16 g_wlo[D_MODEL * D_MODEL];

// ===========================================================================
// Helpers (base-ISA only: ldmatrix / mma.sync / cp.async — NO tcgen05)
// ===========================================================================
__device__ __forceinline__ uint32_t smem_u32(const void* p) {
    uint32_t a;
    asm("{ .reg .u64 t; cvta.to.shared.u64 t, %1; cvt.u32.u64 %0, t; }"
        : "=r"(a) : "l"(p));
    return a;
}
__device__ __forceinline__ uint32_t sw64(uint32_t off) {
    return off ^ ((off >> 3) & 0x30);   // conflict-free ldmatrix on 64B rows
}
__device__ __forceinline__ void ldm_x4(uint32_t r[4], uint32_t addr) {
    asm volatile("ldmatrix.sync.aligned.m8n8.x4.shared.b16 {%0,%1,%2,%3}, [%4];"
        : "=r"(r[0]), "=r"(r[1]), "=r"(r[2]), "=r"(r[3]) : "r"(addr));
}
__device__ __forceinline__ void mma_bf16(float c[4], const uint32_t a[4],
                                         uint32_t b0, uint32_t b1) {
    asm volatile(
        "mma.sync.aligned.m16n8k16.row.col.f32.bf16.bf16.f32 "
        "{%0,%1,%2,%3}, {%4,%5,%6,%7}, {%8,%9}, {%0,%1,%2,%3};"
        : "+f"(c[0]), "+f"(c[1]), "+f"(c[2]), "+f"(c[3])
        : "r"(a[0]), "r"(a[1]), "r"(a[2]), "r"(a[3]), "r"(b0), "r"(b1));
}
__device__ __forceinline__ void cp16(uint32_t saddr, const void* gaddr) {
    asm volatile("cp.async.cg.shared.global [%0], [%1], 16;"
                 :: "r"(saddr), "l"(gaddr));
}

// ===========================================================================
// fp32 -> (bf16 hi, bf16 lo) pre-conversion, vectorized
// ===========================================================================
__global__ __launch_bounds__(256) void cvt_hilo_kernel(
    const float* __restrict__ in, __nv_bfloat16* __restrict__ hi,
    __nv_bfloat16* __restrict__ lo, int n4)
{
    int i = blockIdx.x * 256 + threadIdx.x;
    if (i >= n4) return;
    float4 v = ((const float4*)in)[i];
    __nv_bfloat162 h01 = __floats2bfloat162_rn(v.x, v.y);
    __nv_bfloat162 h23 = __floats2bfloat162_rn(v.z, v.w);
    float2 f01 = __bfloat1622float2(h01);
    float2 f23 = __bfloat1622float2(h23);
    __nv_bfloat162 l01 = __floats2bfloat162_rn(v.x - f01.x, v.y - f01.y);
    __nv_bfloat162 l23 = __floats2bfloat162_rn(v.z - f23.x, v.w - f23.y);
    uint2 hh, ll;
    hh.x = *reinterpret_cast<uint32_t*>(&h01);
    hh.y = *reinterpret_cast<uint32_t*>(&h23);
    ll.x = *reinterpret_cast<uint32_t*>(&l01);
    ll.y = *reinterpret_cast<uint32_t*>(&l23);
    ((uint2*)hi)[i] = hh;
    ((uint2*)lo)[i] = ll;
}

// ===========================================================================
// bf16 hi/lo tensor-core GEMM: Y[M,N] = X[M,K] @ W[N,K]^T + bias
// 128x128x32 CTA tile, 8 warps (warp tile 64x32), cp.async double buffer.
// ===========================================================================
constexpr int BKC    = 32;
constexpr int NC     = D_MODEL / BKC;       // 32
constexpr int TILE8K = 128 * BKC * 2;       // 8192 bytes per bf16 tile
constexpr int STAGE_BYTES = 4 * TILE8K;     // Ahi Alo Bhi Blo = 32KB
constexpr int GEMM_SMEM   = 2 * STAGE_BYTES + 1024;

__global__ __launch_bounds__(256) void gemm_bf16_tc(
    const __nv_bfloat16* __restrict__ Ahi, const __nv_bfloat16* __restrict__ Alo,
    const __nv_bfloat16* __restrict__ Bhi, const __nv_bfloat16* __restrict__ Blo,
    const float* __restrict__ bias, float* __restrict__ Y,
    int M, int N, int K)
{
    extern __shared__ char smraw[];
    const uint32_t sb = (smem_u32(smraw) + 1023) & ~1023u;
    const int tid = threadIdx.x, lane = tid & 31, wid = tid >> 5;
    const int m0 = blockIdx.y * 128, n0 = blockIdx.x * 128;
    const int wm = (wid >> 2) * 64;   // warp M offset (0/64)
    const int wn = (wid & 3) * 32;    // warp N offset

    const int lrow = tid >> 2;        // 0..63
    const int c16  = tid & 3;         // 16B chunk within 64B row

    auto cp_stage = [&](int c, int s) {
        const int kc = c * BKC;
        const uint32_t st = sb + s * STAGE_BYTES;
#pragma unroll
        for (int i = 0; i < 2; ++i) {
            const int row = i * 64 + lrow;
            const uint32_t so = sw64(row * 64 + c16 * 16);
            const size_t ga = (size_t)(m0 + row) * K + kc + c16 * 8;
            const size_t gb = (size_t)(n0 + row) * K + kc + c16 * 8;
            cp16(st + so,              Ahi + ga);
            cp16(st + TILE8K + so,     Alo + ga);
            cp16(st + 2 * TILE8K + so, Bhi + gb);
            cp16(st + 3 * TILE8K + so, Blo + gb);
        }
        asm volatile("cp.async.commit_group;" ::: "memory");
    };

    float acc[4][4][4];
#pragma unroll
    for (int a = 0; a < 4; ++a)
#pragma unroll
        for (int b = 0; b < 4; ++b)
#pragma unroll
            for (int d = 0; d < 4; ++d) acc[a][b][d] = 0.0f;

    cp_stage(0, 0);

    for (int c = 0; c < NC; ++c) {
        asm volatile("cp.async.wait_group 0;" ::: "memory");
        __syncthreads();
        if (c + 1 < NC) cp_stage(c + 1, (c + 1) & 1);

        const uint32_t st = sb + (c & 1) * STAGE_BYTES;
#pragma unroll
        for (int ks = 0; ks < 2; ++ks) {
            uint32_t ahi[4][4], alo[4][4];
#pragma unroll
            for (int mt = 0; mt < 4; ++mt) {
                const uint32_t off = sw64((wm + mt * 16 + (lane & 15)) * 64 +
                                          ks * 32 + (lane >> 4) * 16);
                ldm_x4(ahi[mt], st + off);
                ldm_x4(alo[mt], st + TILE8K + off);
            }
            uint32_t bhi[2][4], blo[2][4];
#pragma unroll
            for (int ntp = 0; ntp < 2; ++ntp) {
                const uint32_t off = sw64((wn + ntp * 16 + ((lane >> 4) << 3) +
                                           (lane & 7)) * 64 +
                                          ks * 32 + ((lane >> 3) & 1) * 16);
                ldm_x4(bhi[ntp], st + 2 * TILE8K + off);
                ldm_x4(blo[ntp], st + 3 * TILE8K + off);
            }
#pragma unroll
            for (int mt = 0; mt < 4; ++mt)
#pragma unroll
                for (int nt = 0; nt < 4; ++nt) {
                    const int p = nt >> 1, q = (nt & 1) * 2;
                    mma_bf16(acc[mt][nt], ahi[mt], bhi[p][q], bhi[p][q + 1]);
                    mma_bf16(acc[mt][nt], ahi[mt], blo[p][q], blo[p][q + 1]);
                    mma_bf16(acc[mt][nt], alo[mt], bhi[p][q], bhi[p][q + 1]);
                }
        }
    }

    // Epilogue: add bias, write fp32
#pragma unroll
    for (int mt = 0; mt < 4; ++mt) {
        const int row = m0 + wm + mt * 16 + (lane >> 2);
#pragma unroll
        for (int nt = 0; nt < 4; ++nt) {
            const int col = n0 + wn + nt * 8 + (lane & 3) * 2;
            const float b0v = __ldg(&bias[col]);
            const float b1v = __ldg(&bias[col + 1]);
            float2 v0 = make_float2(acc[mt][nt][0] + b0v, acc[mt][nt][1] + b1v);
            float2 v1 = make_float2(acc[mt][nt][2] + b0v, acc[mt][nt][3] + b1v);
            *(float2*)(Y + (size_t)row * N + col)       = v0;
            *(float2*)(Y + (size_t)(row + 8) * N + col) = v1;
        }
    }
}

// ===========================================================================
// Flash attention (fp32 SIMT — unchanged passing version; R4 target)
// ===========================================================================
constexpr int TQ = 64;
constexpr int TK = 64;
constexpr int QPAD = DKH + 4;
constexpr int PPAD = TK + 1;

constexpr int SM_Q = 0;
constexpr int SM_K = SM_Q + TQ * QPAD;
constexpr int SM_V = SM_K + TK * QPAD;
constexpr int SM_P = SM_V + TK * QPAD;
constexpr int SM_TOTAL_FLOATS = SM_P + TQ * PPAD;
constexpr int SM_BYTES = SM_TOTAL_FLOATS * 4;

__global__ __launch_bounds__(256) void attn_kernel(
    const float* __restrict__ q, const float* __restrict__ k,
    const float* __restrict__ v, float* __restrict__ o)
{
    extern __shared__ float sm[];
    float (*q_s)[QPAD] = (float(*)[QPAD])(sm + SM_Q);
    float (*k_s)[QPAD] = (float(*)[QPAD])(sm + SM_K);
    float (*v_s)[QPAD] = (float(*)[QPAD])(sm + SM_V);
    float (*p_s)[PPAD] = (float(*)[PPAD])(sm + SM_P);

    const int tid = threadIdx.x;
    const int tx  = tid & 15;
    const int ty  = tid >> 4;
    const int qt  = blockIdx.x;
    const int h   = blockIdx.y;
    const int b   = blockIdx.z;

    const size_t base = ((size_t)b * S_LEN) * D_MODEL + (size_t)h * DKH;
    const float* qb = q + base + (size_t)(qt * TQ) * D_MODEL;
    const float* kb = k + base;
    const float* vb = v + base;

#pragma unroll
    for (int f = tid; f < TQ * DKH / 4; f += 256) {
        int r = f >> 4;
        int c = (f & 15) << 2;
        *(float4*)&q_s[r][c] = *(const float4*)(qb + (size_t)r * D_MODEL + c);
    }

    float acc[4][4];
    float m_i[4], l_i[4];
#pragma unroll
    for (int i = 0; i < 4; ++i) {
        m_i[i] = -1e30f;
        l_i[i] = 0.0f;
#pragma unroll
        for (int j = 0; j < 4; ++j) acc[i][j] = 0.0f;
    }

    const float scale = 0.125f;

    for (int kt = 0; kt < S_LEN / TK; ++kt) {
        const float* kp = kb + (size_t)(kt * TK) * D_MODEL;
        const float* vp = vb + (size_t)(kt * TK) * D_MODEL;
#pragma unroll
        for (int f = tid; f < TK * DKH / 4; f += 256) {
            int r = f >> 4;
            int c = (f & 15) << 2;
            *(float4*)&k_s[r][c] = *(const float4*)(kp + (size_t)r * D_MODEL + c);
            *(float4*)&v_s[r][c] = *(const float4*)(vp + (size_t)r * D_MODEL + c);
        }
        __syncthreads();

        float s[4][4];
#pragma unroll
        for (int i = 0; i < 4; ++i)
#pragma unroll
            for (int j = 0; j < 4; ++j) s[i][j] = 0.0f;

#pragma unroll
        for (int d4 = 0; d4 < DKH; d4 += 4) {
            float4 a[4], bbk[4];
#pragma unroll
            for (int i = 0; i < 4; ++i) a[i]   = *(const float4*)&q_s[ty * 4 + i][d4];
#pragma unroll
            for (int j = 0; j < 4; ++j) bbk[j] = *(const float4*)&k_s[tx * 4 + j][d4];
#pragma unroll
            for (int i = 0; i < 4; ++i)
#pragma unroll
                for (int j = 0; j < 4; ++j) {
                    s[i][j] += a[i].x * bbk[j].x;
                    s[i][j] += a[i].y * bbk[j].y;
                    s[i][j] += a[i].z * bbk[j].z;
                    s[i][j] += a[i].w * bbk[j].w;
                }
        }

#pragma unroll
        for (int i = 0; i < 4; ++i) {
            float s0 = s[i][0] * scale, s1 = s[i][1] * scale;
            float s2 = s[i][2] * scale, s3 = s[i][3] * scale;
            float tmax = fmaxf(fmaxf(s0, s1), fmaxf(s2, s3));
#pragma unroll
            for (int off = 8; off >= 1; off >>= 1)
                tmax = fmaxf(tmax, __shfl_xor_sync(0xffffffffu, tmax, off, 16));
            float newm = fmaxf(m_i[i], tmax);
            float p0 = __expf(s0 - newm), p1 = __expf(s1 - newm);
            float p2 = __expf(s2 - newm), p3 = __expf(s3 - newm);
            float psum = p0 + p1 + p2 + p3;
#pragma unroll
            for (int off = 8; off >= 1; off >>= 1)
                psum += __shfl_xor_sync(0xffffffffu, psum, off, 16);
            float alpha = __expf(m_i[i] - newm);
            l_i[i] = l_i[i] * alpha + psum;
            m_i[i] = newm;
#pragma unroll
            for (int j = 0; j < 4; ++j) acc[i][j] *= alpha;
            int r = ty * 4 + i;
            p_s[r][tx * 4 + 0] = p0;
            p_s[r][tx * 4 + 1] = p1;
            p_s[r][tx * 4 + 2] = p2;
            p_s[r][tx * 4 + 3] = p3;
        }
        __syncthreads();

#pragma unroll 8
        for (int jk = 0; jk < TK; ++jk) {
            float4 bv = *(const float4*)&v_s[jk][tx * 4];
#pragma unroll
            for (int i = 0; i < 4; ++i) {
                float a = p_s[ty * 4 + i][jk];
                acc[i][0] += a * bv.x;
                acc[i][1] += a * bv.y;
                acc[i][2] += a * bv.z;
                acc[i][3] += a * bv.w;
            }
        }
        __syncthreads();
    }

#pragma unroll
    for (int i = 0; i < 4; ++i) {
        float inv = 1.0f / l_i[i];
        float4 r4 = make_float4(acc[i][0] * inv, acc[i][1] * inv,
                                acc[i][2] * inv, acc[i][3] * inv);
        size_t row = (size_t)(qt * TQ + ty * 4 + i);
        *(float4*)(o + base + row * D_MODEL + tx * 4) = r4;
    }
}

// ===========================================================================
// kernel_launch: Q K V Wq bq Wk bk Wv bv Wo bo ; output float32
// ===========================================================================
extern "C" void kernel_launch(void* const* d_in, const int* in_sizes, int n_in,
                              void* d_out, int out_size)
{
    const float* Q  = (const float*)d_in[0];
    const float* K  = (const float*)d_in[1];
    const float* V  = (const float*)d_in[2];
    const float* Wq = (const float*)d_in[3];
    const float* bq = (const float*)d_in[4];
    const float* Wk = (const float*)d_in[5];
    const float* bk = (const float*)d_in[6];
    const float* Wv = (const float*)d_in[7];
    const float* bv = (const float*)d_in[8];
    const float* Wo = (const float*)d_in[9];
    const float* bo = (const float*)d_in[10];
    float* out = (float*)d_out;

    float *gq, *gk, *gv, *ga;
    __nv_bfloat16 *xhi, *xlo, *whi, *wlo;
    cudaGetSymbolAddress((void**)&gq,  g_q);
    cudaGetSymbolAddress((void**)&gk,  g_k);
    cudaGetSymbolAddress((void**)&gv,  g_v);
    cudaGetSymbolAddress((void**)&ga,  g_attn);
    cudaGetSymbolAddress((void**)&xhi, g_xhi);
    cudaGetSymbolAddress((void**)&xlo, g_xlo);
    cudaGetSymbolAddress((void**)&whi, g_whi);
    cudaGetSymbolAddress((void**)&wlo, g_wlo);

    cudaFuncSetAttribute(gemm_bf16_tc,
                         cudaFuncAttributeMaxDynamicSharedMemorySize, GEMM_SMEM);
    cudaFuncSetAttribute(attn_kernel,
                         cudaFuncAttributeMaxDynamicSharedMemorySize, SM_BYTES);

    const int nX4 = NTOK * D_MODEL / 4;      // 1,048,576
    const int nW4 = D_MODEL * D_MODEL / 4;   // 262,144
    dim3 ggrid(D_MODEL / 128, NTOK / 128);   // (8, 32)

    // Q projection
    cvt_hilo_kernel<<<nX4 / 256, 256>>>(Q,  xhi, xlo, nX4);
    cvt_hilo_kernel<<<nW4 / 256, 256>>>(Wq, whi, wlo, nW4);
    gemm_bf16_tc<<<ggrid, 256, GEMM_SMEM>>>(xhi, xlo, whi, wlo, bq, gq,
                                            NTOK, D_MODEL, D_MODEL);
    // K projection
    cvt_hilo_kernel<<<nX4 / 256, 256>>>(K,  xhi, xlo, nX4);
    cvt_hilo_kernel<<<nW4 / 256, 256>>>(Wk, whi, wlo, nW4);
    gemm_bf16_tc<<<ggrid, 256, GEMM_SMEM>>>(xhi, xlo, whi, wlo, bk, gk,
                                            NTOK, D_MODEL, D_MODEL);
    // V projection
    cvt_hilo_kernel<<<nX4 / 256, 256>>>(V,  xhi, xlo, nX4);
    cvt_hilo_kernel<<<nW4 / 256, 256>>>(Wv, whi, wlo, nW4);
    gemm_bf16_tc<<<ggrid, 256, GEMM_SMEM>>>(xhi, xlo, whi, wlo, bv, gv,
                                            NTOK, D_MODEL, D_MODEL);

    // Attention
    dim3 agrid(S_LEN / TQ, NHEAD, B_SZ);     // (32, 16, 2)
    attn_kernel<<<agrid, 256, SM_BYTES>>>(gq, gk, gv, ga);

    // Output projection
    cvt_hilo_kernel<<<nX4 / 256, 256>>>(ga, xhi, xlo, nX4);
    cvt_hilo_kernel<<<nW4 / 256, 256>>>(Wo, whi, wlo, nW4);
    gemm_bf16_tc<<<ggrid, 256, GEMM_SMEM>>>(xhi, xlo, whi, wlo, bo, out,
                                            NTOK, D_MODEL, D_MODEL);
}

// round 5
// speedup vs baseline: 4.1286x; 3.2056x over previous
#include <cuda_runtime.h>
#include <cuda_bf16.h>
#include <cstdint>

// Problem constants
constexpr int B_SZ    = 2;
constexpr int S_LEN   = 2048;
constexpr int D_MODEL = 1024;
constexpr int NHEAD   = 16;
constexpr int DKH     = 64;
constexpr int NTOK    = B_SZ * S_LEN;    // 4096

// Scratch (device globals: allocation-free per harness rules)
__device__ __nv_bfloat16 g_xhi[NTOK * D_MODEL];
__device__ __nv_bfloat16 g_xlo[NTOK * D_MODEL];
__device__ __nv_bfloat16 g_whi[D_MODEL * D_MODEL];
__device__ __nv_bfloat16 g_wlo[D_MODEL * D_MODEL];
__device__ __nv_bfloat16 g_qhi[NTOK * D_MODEL];
__device__ __nv_bfloat16 g_qlo[NTOK * D_MODEL];
__device__ __nv_bfloat16 g_khi[NTOK * D_MODEL];
__device__ __nv_bfloat16 g_klo[NTOK * D_MODEL];
__device__ __nv_bfloat16 g_vhi[NTOK * D_MODEL];
__device__ __nv_bfloat16 g_vlo[NTOK * D_MODEL];

// ===========================================================================
// Helpers (base-ISA only: ldmatrix / mma.sync / cp.async)
// ===========================================================================
__device__ __forceinline__ uint32_t smem_u32(const void* p) {
    uint32_t a;
    asm("{ .reg .u64 t; cvta.to.shared.u64 t, %1; cvt.u32.u64 %0, t; }"
        : "=r"(a) : "l"(p));
    return a;
}
__device__ __forceinline__ uint32_t sw64(uint32_t off) {
    return off ^ ((off >> 3) & 0x30);
}
__device__ __forceinline__ uint32_t sw128(uint32_t off) {
    return off ^ ((off >> 3) & 0x70);
}
__device__ __forceinline__ void ldm_x4(uint32_t r[4], uint32_t addr) {
    asm volatile("ldmatrix.sync.aligned.m8n8.x4.shared.b16 {%0,%1,%2,%3}, [%4];"
        : "=r"(r[0]), "=r"(r[1]), "=r"(r[2]), "=r"(r[3]) : "r"(addr));
}
__device__ __forceinline__ void ldm_x4_t(uint32_t r[4], uint32_t addr) {
    asm volatile("ldmatrix.sync.aligned.m8n8.x4.trans.shared.b16 {%0,%1,%2,%3}, [%4];"
        : "=r"(r[0]), "=r"(r[1]), "=r"(r[2]), "=r"(r[3]) : "r"(addr));
}
__device__ __forceinline__ void mma_bf16(float c[4], const uint32_t a[4],
                                         uint32_t b0, uint32_t b1) {
    asm volatile(
        "mma.sync.aligned.m16n8k16.row.col.f32.bf16.bf16.f32 "
        "{%0,%1,%2,%3}, {%4,%5,%6,%7}, {%8,%9}, {%0,%1,%2,%3};"
        : "+f"(c[0]), "+f"(c[1]), "+f"(c[2]), "+f"(c[3])
        : "r"(a[0]), "r"(a[1]), "r"(a[2]), "r"(a[3]), "r"(b0), "r"(b1));
}
__device__ __forceinline__ void cp16(uint32_t saddr, const void* gaddr) {
    asm volatile("cp.async.cg.shared.global [%0], [%1], 16;"
                 :: "r"(saddr), "l"(gaddr));
}
__device__ __forceinline__ float ex2(float x) {
    float y;
    asm("ex2.approx.ftz.f32 %0, %1;" : "=f"(y) : "f"(x));
    return y;
}
__device__ __forceinline__ void pack_hilo(float a, float b,
                                          uint32_t& hi, uint32_t& lo) {
    __nv_bfloat162 h = __floats2bfloat162_rn(a, b);
    float2 f = __bfloat1622float2(h);
    __nv_bfloat162 l = __floats2bfloat162_rn(a - f.x, b - f.y);
    hi = *reinterpret_cast<uint32_t*>(&h);
    lo = *reinterpret_cast<uint32_t*>(&l);
}

// ===========================================================================
// fp32 -> (bf16 hi, bf16 lo) pre-conversion (inputs + weights)
// ===========================================================================
__global__ __launch_bounds__(256) void cvt_hilo_kernel(
    const float* __restrict__ in, __nv_bfloat16* __restrict__ hi,
    __nv_bfloat16* __restrict__ lo, int n4)
{
    int i = blockIdx.x * 256 + threadIdx.x;
    if (i >= n4) return;
    float4 v = ((const float4*)in)[i];
    uint2 hh, ll;
    pack_hilo(v.x, v.y, hh.x, ll.x);
    pack_hilo(v.z, v.w, hh.y, ll.y);
    ((uint2*)hi)[i] = hh;
    ((uint2*)lo)[i] = ll;
}

// ===========================================================================
// bf16 hi/lo tensor-core GEMM: Y = X @ W^T + bias
// 128x128x32 CTA tile, 8 warps, cp.async double buffer.
// Epilogue: fp32 (Y) or bf16 hi/lo (Yhi/Ylo) per flag.
// ===========================================================================
constexpr int BKC    = 32;
constexpr int NC     = D_MODEL / BKC;       // 32
constexpr int TILE8K = 128 * BKC * 2;       // 8192 bytes
constexpr int STAGE_BYTES = 4 * TILE8K;     // 32KB
constexpr int GEMM_SMEM   = 2 * STAGE_BYTES + 1024;

__global__ __launch_bounds__(256) void gemm_bf16_tc(
    const __nv_bfloat16* __restrict__ Ahi, const __nv_bfloat16* __restrict__ Alo,
    const __nv_bfloat16* __restrict__ Bhi, const __nv_bfloat16* __restrict__ Blo,
    const float* __restrict__ bias, float* __restrict__ Y,
    __nv_bfloat16* __restrict__ Yhi, __nv_bfloat16* __restrict__ Ylo,
    int M, int N, int K)
{
    extern __shared__ char smraw[];
    const uint32_t sb = (smem_u32(smraw) + 1023) & ~1023u;
    const int tid = threadIdx.x, lane = tid & 31, wid = tid >> 5;
    const int m0 = blockIdx.y * 128, n0 = blockIdx.x * 128;
    const int wm = (wid >> 2) * 64;
    const int wn = (wid & 3) * 32;

    const int lrow = tid >> 2;
    const int c16  = tid & 3;

    auto cp_stage = [&](int c, int s) {
        const int kc = c * BKC;
        const uint32_t st = sb + s * STAGE_BYTES;
#pragma unroll
        for (int i = 0; i < 2; ++i) {
            const int row = i * 64 + lrow;
            const uint32_t so = sw64(row * 64 + c16 * 16);
            const size_t ga = (size_t)(m0 + row) * K + kc + c16 * 8;
            const size_t gb = (size_t)(n0 + row) * K + kc + c16 * 8;
            cp16(st + so,              Ahi + ga);
            cp16(st + TILE8K + so,     Alo + ga);
            cp16(st + 2 * TILE8K + so, Bhi + gb);
            cp16(st + 3 * TILE8K + so, Blo + gb);
        }
        asm volatile("cp.async.commit_group;" ::: "memory");
    };

    float acc[4][4][4];
#pragma unroll
    for (int a = 0; a < 4; ++a)
#pragma unroll
        for (int b = 0; b < 4; ++b)
#pragma unroll
            for (int d = 0; d < 4; ++d) acc[a][b][d] = 0.0f;

    cp_stage(0, 0);

    for (int c = 0; c < NC; ++c) {
        asm volatile("cp.async.wait_group 0;" ::: "memory");
        __syncthreads();
        if (c + 1 < NC) cp_stage(c + 1, (c + 1) & 1);

        const uint32_t st = sb + (c & 1) * STAGE_BYTES;
#pragma unroll
        for (int ks = 0; ks < 2; ++ks) {
            uint32_t ahi[4][4], alo[4][4];
#pragma unroll
            for (int mt = 0; mt < 4; ++mt) {
                const uint32_t off = sw64((wm + mt * 16 + (lane & 15)) * 64 +
                                          ks * 32 + (lane >> 4) * 16);
                ldm_x4(ahi[mt], st + off);
                ldm_x4(alo[mt], st + TILE8K + off);
            }
            uint32_t bhi[2][4], blo[2][4];
#pragma unroll
            for (int ntp = 0; ntp < 2; ++ntp) {
                const uint32_t off = sw64((wn + ntp * 16 + ((lane >> 4) << 3) +
                                           (lane & 7)) * 64 +
                                          ks * 32 + ((lane >> 3) & 1) * 16);
                ldm_x4(bhi[ntp], st + 2 * TILE8K + off);
                ldm_x4(blo[ntp], st + 3 * TILE8K + off);
            }
#pragma unroll
            for (int mt = 0; mt < 4; ++mt)
#pragma unroll
                for (int nt = 0; nt < 4; ++nt) {
                    const int p = nt >> 1, q = (nt & 1) * 2;
                    mma_bf16(acc[mt][nt], ahi[mt], bhi[p][q], bhi[p][q + 1]);
                    mma_bf16(acc[mt][nt], ahi[mt], blo[p][q], blo[p][q + 1]);
                    mma_bf16(acc[mt][nt], alo[mt], bhi[p][q], bhi[p][q + 1]);
                }
        }
    }

    // Epilogue
#pragma unroll
    for (int mt = 0; mt < 4; ++mt) {
        const int row = m0 + wm + mt * 16 + (lane >> 2);
#pragma unroll
        for (int nt = 0; nt < 4; ++nt) {
            const int col = n0 + wn + nt * 8 + (lane & 3) * 2;
            const float b0v = __ldg(&bias[col]);
            const float b1v = __ldg(&bias[col + 1]);
            const float v0 = acc[mt][nt][0] + b0v, v1 = acc[mt][nt][1] + b1v;
            const float v2 = acc[mt][nt][2] + b0v, v3 = acc[mt][nt][3] + b1v;
            if (Yhi) {
                uint32_t hh, ll;
                pack_hilo(v0, v1, hh, ll);
                *(uint32_t*)(Yhi + (size_t)row * N + col) = hh;
                *(uint32_t*)(Ylo + (size_t)row * N + col) = ll;
                pack_hilo(v2, v3, hh, ll);
                *(uint32_t*)(Yhi + (size_t)(row + 8) * N + col) = hh;
                *(uint32_t*)(Ylo + (size_t)(row + 8) * N + col) = ll;
            } else {
                *(float2*)(Y + (size_t)row * N + col)       = make_float2(v0, v1);
                *(float2*)(Y + (size_t)(row + 8) * N + col) = make_float2(v2, v3);
            }
        }
    }
}

// ===========================================================================
// Tensor-core flash attention (bf16 hi/lo on both QK^T and PV)
// CTA: 64 queries x one (head, batch). 4 warps, 16 query rows each.
// K/V tiles of 64 keys, double-buffered cp.async. Online softmax in exp2
// domain, P kept in registers and repacked as MMA A-fragments.
// ===========================================================================
constexpr int ATT_SMEM = 1024 + 16384 + 2 * 32768;   // Q + 2 stages = 82944

__global__ __launch_bounds__(128) void attn_tc(
    const __nv_bfloat16* __restrict__ qh_, const __nv_bfloat16* __restrict__ ql_,
    const __nv_bfloat16* __restrict__ kh_, const __nv_bfloat16* __restrict__ kl_,
    const __nv_bfloat16* __restrict__ vh_, const __nv_bfloat16* __restrict__ vl_,
    __nv_bfloat16* __restrict__ ohi, __nv_bfloat16* __restrict__ olo)
{
    extern __shared__ char smraw[];
    const uint32_t sb = (smem_u32(smraw) + 1023) & ~1023u;
    const int tid = threadIdx.x, lane = tid & 31, wid = tid >> 5;
    const int qt = blockIdx.x, h = blockIdx.y, b = blockIdx.z;
    const size_t bt = (size_t)b * S_LEN;

    const uint32_t sQH = sb, sQL = sb + 8192;

    // Q tile copy (64 rows x 128B, hi+lo) — joins cp group 0
    {
        const int row = tid >> 3, c = tid & 7;
        const size_t gq0 = (bt + (size_t)qt * 64) * D_MODEL + h * DKH + c * 8;
#pragma unroll
        for (int it = 0; it < 4; ++it) {
            const int r = it * 16 + row;
            const uint32_t so = sw128(r * 128 + c * 16);
            cp16(sQH + so, qh_ + gq0 + (size_t)r * D_MODEL);
            cp16(sQL + so, ql_ + gq0 + (size_t)r * D_MODEL);
        }
    }

    auto cp_kv = [&](int kt, int s) {
        const uint32_t st = sb + 16384 + s * 32768;
        const int row = tid >> 3, c = tid & 7;
        const size_t g0 = (bt + (size_t)kt * 64) * D_MODEL + h * DKH + c * 8;
#pragma unroll
        for (int it = 0; it < 4; ++it) {
            const int r = it * 16 + row;
            const uint32_t so = sw128(r * 128 + c * 16);
            const size_t g = g0 + (size_t)r * D_MODEL;
            cp16(st + so,         kh_ + g);
            cp16(st + 8192 + so,  kl_ + g);
            cp16(st + 16384 + so, vh_ + g);
            cp16(st + 24576 + so, vl_ + g);
        }
        asm volatile("cp.async.commit_group;" ::: "memory");
    };

    cp_kv(0, 0);
    cp_kv(1, 1);

    float s[8][4], out[8][4];
    float m0 = -1e30f, m1 = -1e30f, l0 = 0.0f, l1 = 0.0f;
#pragma unroll
    for (int nt = 0; nt < 8; ++nt)
#pragma unroll
        for (int v = 0; v < 4; ++v) out[nt][v] = 0.0f;

    uint32_t qfh[4][4], qfl[4][4];
    constexpr float SC = 0.18033688f;   // 0.125 * log2(e)

    for (int kt = 0; kt < S_LEN / 64; ++kt) {
        asm volatile("cp.async.wait_group 1;" ::: "memory");
        __syncthreads();

        if (kt == 0) {
#pragma unroll
            for (int ks = 0; ks < 4; ++ks) {
                const uint32_t off = sw128((wid * 16 + (lane & 15)) * 128 +
                                           ks * 32 + (lane >> 4) * 16);
                ldm_x4(qfh[ks], sQH + off);
                ldm_x4(qfl[ks], sQL + off);
            }
        }

        const uint32_t KH = sb + 16384 + (kt & 1) * 32768;
        const uint32_t KL = KH + 8192, VH = KH + 16384, VL = KH + 24576;

        // ---- scores S = Q.K^T (hi/lo 3-MMA) ----
#pragma unroll
        for (int nt = 0; nt < 8; ++nt)
#pragma unroll
            for (int v = 0; v < 4; ++v) s[nt][v] = 0.0f;

#pragma unroll
        for (int ntp = 0; ntp < 4; ++ntp) {
            const uint32_t rb = (ntp * 16 + ((lane >> 4) << 3) + (lane & 7)) * 128;
#pragma unroll
            for (int ks = 0; ks < 4; ++ks) {
                const uint32_t off = sw128(rb + ks * 32 + ((lane >> 3) & 1) * 16);
                uint32_t bh[4], bl[4];
                ldm_x4(bh, KH + off);
                ldm_x4(bl, KL + off);
                mma_bf16(s[2 * ntp],     qfh[ks], bh[0], bh[1]);
                mma_bf16(s[2 * ntp],     qfh[ks], bl[0], bl[1]);
                mma_bf16(s[2 * ntp],     qfl[ks], bh[0], bh[1]);
                mma_bf16(s[2 * ntp + 1], qfh[ks], bh[2], bh[3]);
                mma_bf16(s[2 * ntp + 1], qfh[ks], bl[2], bl[3]);
                mma_bf16(s[2 * ntp + 1], qfl[ks], bh[2], bh[3]);
            }
        }

        // ---- online softmax (exp2 domain; rows r=lane>>2 and r+8) ----
        float mx0 = -1e30f, mx1 = -1e30f;
#pragma unroll
        for (int nt = 0; nt < 8; ++nt) {
            s[nt][0] *= SC; s[nt][1] *= SC; s[nt][2] *= SC; s[nt][3] *= SC;
            mx0 = fmaxf(mx0, fmaxf(s[nt][0], s[nt][1]));
            mx1 = fmaxf(mx1, fmaxf(s[nt][2], s[nt][3]));
        }
        mx0 = fmaxf(mx0, __shfl_xor_sync(0xffffffffu, mx0, 1));
        mx0 = fmaxf(mx0, __shfl_xor_sync(0xffffffffu, mx0, 2));
        mx1 = fmaxf(mx1, __shfl_xor_sync(0xffffffffu, mx1, 1));
        mx1 = fmaxf(mx1, __shfl_xor_sync(0xffffffffu, mx1, 2));
        const float nm0 = fmaxf(m0, mx0), nm1 = fmaxf(m1, mx1);
        const float a0 = ex2(m0 - nm0), a1 = ex2(m1 - nm1);
        m0 = nm0; m1 = nm1;
        float rs0 = 0.0f, rs1 = 0.0f;
#pragma unroll
        for (int nt = 0; nt < 8; ++nt) {
            s[nt][0] = ex2(s[nt][0] - m0);
            s[nt][1] = ex2(s[nt][1] - m0);
            s[nt][2] = ex2(s[nt][2] - m1);
            s[nt][3] = ex2(s[nt][3] - m1);
            rs0 += s[nt][0] + s[nt][1];
            rs1 += s[nt][2] + s[nt][3];
            out[nt][0] *= a0; out[nt][1] *= a0;
            out[nt][2] *= a1; out[nt][3] *= a1;
        }
        rs0 += __shfl_xor_sync(0xffffffffu, rs0, 1);
        rs0 += __shfl_xor_sync(0xffffffffu, rs0, 2);
        rs1 += __shfl_xor_sync(0xffffffffu, rs1, 1);
        rs1 += __shfl_xor_sync(0xffffffffu, rs1, 2);
        l0 = l0 * a0 + rs0;
        l1 = l1 * a1 + rs1;

        // ---- PV: out += P.V (P hi/lo in regs, V via ldmatrix.trans) ----
#pragma unroll
        for (int ks = 0; ks < 4; ++ks) {
            uint32_t ph[4], pl[4];
            pack_hilo(s[2 * ks][0],     s[2 * ks][1],     ph[0], pl[0]);
            pack_hilo(s[2 * ks][2],     s[2 * ks][3],     ph[1], pl[1]);
            pack_hilo(s[2 * ks + 1][0], s[2 * ks + 1][1], ph[2], pl[2]);
            pack_hilo(s[2 * ks + 1][2], s[2 * ks + 1][3], ph[3], pl[3]);
            const uint32_t vrow = (ks * 16 + ((lane >> 3) & 1) * 8 + (lane & 7)) * 128;
#pragma unroll
            for (int np = 0; np < 4; ++np) {
                const uint32_t off = sw128(vrow + np * 32 + (lane >> 4) * 16);
                uint32_t vh4[4], vl4[4];
                ldm_x4_t(vh4, VH + off);
                ldm_x4_t(vl4, VL + off);
                mma_bf16(out[2 * np],     ph, vh4[0], vh4[1]);
                mma_bf16(out[2 * np],     ph, vl4[0], vl4[1]);
                mma_bf16(out[2 * np],     pl, vh4[0], vh4[1]);
                mma_bf16(out[2 * np + 1], ph, vh4[2], vh4[3]);
                mma_bf16(out[2 * np + 1], ph, vl4[2], vl4[3]);
                mma_bf16(out[2 * np + 1], pl, vh4[2], vh4[3]);
            }
        }

        __syncthreads();
        if (kt + 2 < S_LEN / 64) cp_kv(kt + 2, kt & 1);
        else asm volatile("cp.async.commit_group;" ::: "memory");
    }

    // ---- epilogue: normalize, emit bf16 hi/lo for the O-projection ----
    const float i0 = 1.0f / l0, i1 = 1.0f / l1;
    const int r0 = qt * 64 + wid * 16 + (lane >> 2);
    const size_t t0 = (bt + r0) * D_MODEL;
    const size_t t1 = t0 + 8 * D_MODEL;
#pragma unroll
    for (int nt = 0; nt < 8; ++nt) {
        const int col = h * DKH + nt * 8 + (lane & 3) * 2;
        uint32_t hh, ll;
        pack_hilo(out[nt][0] * i0, out[nt][1] * i0, hh, ll);
        *(uint32_t*)(ohi + t0 + col) = hh;
        *(uint32_t*)(olo + t0 + col) = ll;
        pack_hilo(out[nt][2] * i1, out[nt][3] * i1, hh, ll);
        *(uint32_t*)(ohi + t1 + col) = hh;
        *(uint32_t*)(olo + t1 + col) = ll;
    }
}

// ===========================================================================
// kernel_launch: Q K V Wq bq Wk bk Wv bv Wo bo ; output float32
// ===========================================================================
extern "C" void kernel_launch(void* const* d_in, const int* in_sizes, int n_in,
                              void* d_out, int out_size)
{
    const float* Q  = (const float*)d_in[0];
    const float* K  = (const float*)d_in[1];
    const float* V  = (const float*)d_in[2];
    const float* Wq = (const float*)d_in[3];
    const float* bq = (const float*)d_in[4];
    const float* Wk = (const float*)d_in[5];
    const float* bk = (const float*)d_in[6];
    const float* Wv = (const float*)d_in[7];
    const float* bv = (const float*)d_in[8];
    const float* Wo = (const float*)d_in[9];
    const float* bo = (const float*)d_in[10];
    float* out = (float*)d_out;

    __nv_bfloat16 *xhi, *xlo, *whi, *wlo;
    __nv_bfloat16 *qhi, *qlo, *khi, *klo, *vhi, *vlo;
    cudaGetSymbolAddress((void**)&xhi, g_xhi);
    cudaGetSymbolAddress((void**)&xlo, g_xlo);
    cudaGetSymbolAddress((void**)&whi, g_whi);
    cudaGetSymbolAddress((void**)&wlo, g_wlo);
    cudaGetSymbolAddress((void**)&qhi, g_qhi);
    cudaGetSymbolAddress((void**)&qlo, g_qlo);
    cudaGetSymbolAddress((void**)&khi, g_khi);
    cudaGetSymbolAddress((void**)&klo, g_klo);
    cudaGetSymbolAddress((void**)&vhi, g_vhi);
    cudaGetSymbolAddress((void**)&vlo, g_vlo);

    cudaFuncSetAttribute(gemm_bf16_tc,
                         cudaFuncAttributeMaxDynamicSharedMemorySize, GEMM_SMEM);
    cudaFuncSetAttribute(attn_tc,
                         cudaFuncAttributeMaxDynamicSharedMemorySize, ATT_SMEM);

    const int nX4 = NTOK * D_MODEL / 4;
    const int nW4 = D_MODEL * D_MODEL / 4;
    dim3 ggrid(D_MODEL / 128, NTOK / 128);   // (8, 32)

    // Q projection -> bf16 hi/lo
    cvt_hilo_kernel<<<nX4 / 256, 256>>>(Q,  xhi, xlo, nX4);
    cvt_hilo_kernel<<<nW4 / 256, 256>>>(Wq, whi, wlo, nW4);
    gemm_bf16_tc<<<ggrid, 256, GEMM_SMEM>>>(xhi, xlo, whi, wlo, bq,
                                            nullptr, qhi, qlo,
                                            NTOK, D_MODEL, D_MODEL);
    // K projection
    cvt_hilo_kernel<<<nX4 / 256, 256>>>(K,  xhi, xlo, nX4);
    cvt_hilo_kernel<<<nW4 / 256, 256>>>(Wk, whi, wlo, nW4);
    gemm_bf16_tc<<<ggrid, 256, GEMM_SMEM>>>(xhi, xlo, whi, wlo, bk,
                                            nullptr, khi, klo,
                                            NTOK, D_MODEL, D_MODEL);
    // V projection
    cvt_hilo_kernel<<<nX4 / 256, 256>>>(V,  xhi, xlo, nX4);
    cvt_hilo_kernel<<<nW4 / 256, 256>>>(Wv, whi, wlo, nW4);
    gemm_bf16_tc<<<ggrid, 256, GEMM_SMEM>>>(xhi, xlo, whi, wlo, bv,
                                            nullptr, vhi, vlo,
                                            NTOK, D_MODEL, D_MODEL);

    // Attention (writes bf16 hi/lo into xhi/xlo for the O-projection)
    dim3 agrid(S_LEN / 64, NHEAD, B_SZ);     // (32, 16, 2)
    attn_tc<<<agrid, 128, ATT_SMEM>>>(qhi, qlo, khi, klo, vhi, vlo, xhi, xlo);

    // Output projection -> fp32
    cvt_hilo_kernel<<<nW4 / 256, 256>>>(Wo, whi, wlo, nW4);
    gemm_bf16_tc<<<ggrid, 256, GEMM_SMEM>>>(xhi, xlo, whi, wlo, bo,
                                            out, nullptr, nullptr,
                                            NTOK, D_MODEL, D_MODEL);
}